// round 1
// baseline (speedup 1.0000x reference)
#include <cuda_runtime.h>
#include <cstdint>

// ----------------------------------------------------------------------------
// VectorQuantizerEMA: z [64,4096,64] f32, embedding [512,64] f32
// Outputs (concatenated f32, tuple order):
//   z_q_st [16777216], loss [1], indices [262144], new_embedding [32768],
//   new_cluster_size [512], new_embedding_avg [32768]   -> total 17105409
// ----------------------------------------------------------------------------

#define NC      512
#define CD      64
#define NROWS   (64 * 4096)              // 262144
#define NELEM   (NROWS * CD)             // 16777216

// output offsets
#define O_ZQ    ((size_t)0)
#define O_LOSS  ((size_t)16777216)
#define O_IDX   ((size_t)16777217)
#define O_NEMB  ((size_t)17039361)
#define O_NCS   ((size_t)17072129)
#define O_NAVG  ((size_t)17072641)

typedef unsigned long long ull;

// scratch (device globals: no allocation in kernel_launch)
__device__ __align__(16) float g_esum[NC * CD];
__device__ float g_counts[NC];
__device__ float g_h[NC];      // 0.5 * ||e_j||^2
__device__ float g_sse;

// ---- packed f32x2 helpers (Blackwell) --------------------------------------
__device__ __forceinline__ void fma2(ull& acc, ull a, ull b) {
    asm("fma.rn.f32x2 %0, %1, %2, %0;" : "+l"(acc) : "l"(a), "l"(b));
}
__device__ __forceinline__ ull add2(ull a, ull b) {
    ull d; asm("add.rn.f32x2 %0, %1, %2;" : "=l"(d) : "l"(a), "l"(b)); return d;
}
__device__ __forceinline__ float2 unpack2(ull v) {
    float2 r; asm("mov.b64 {%0, %1}, %2;" : "=f"(r.x), "=f"(r.y) : "l"(v)); return r;
}

// ----------------------------------------------------------------------------
// Kernel 1: zero scratch, precompute half-norms
// ----------------------------------------------------------------------------
__global__ void vq_init(const float* __restrict__ emb) {
    int t = blockIdx.x * blockDim.x + threadIdx.x;
    if (t < NC * CD) g_esum[t] = 0.0f;
    if (t == 0) g_sse = 0.0f;
    if (blockIdx.x == 0 && t < NC) {
        g_counts[t] = 0.0f;
        const float4* e = (const float4*)(emb + (size_t)t * CD);
        float s = 0.0f;
#pragma unroll
        for (int i = 0; i < CD / 4; i++) {
            float4 v = e[i];
            s += v.x * v.x + v.y * v.y + v.z * v.z + v.w * v.w;
        }
        g_h[t] = 0.5f * s;
    }
}

// ----------------------------------------------------------------------------
// Kernel 2: main — one thread per row. Codebook in smem (128KB), broadcast
// LDS.128 + packed fma.rn.f32x2 inner loop, argmax of (f.e - 0.5||e||^2).
// ----------------------------------------------------------------------------
__global__ void __launch_bounds__(512, 1)
vq_main(const float* __restrict__ z, float* __restrict__ out) {
    extern __shared__ __align__(16) ull smemraw[];
    ull*   sE   = smemraw;                         // 512 codes * 32 ull = 128KB
    float* sH   = (float*)(sE + NC * (CD / 2));    // 512 f
    float* sCnt = sH + NC;                         // 512 f

    // stage codebook + half-norms, zero smem histogram
    {
        // reuse: codebook already resident in L2; read via g_esum? No — read
        // from the global embedding copy the init kernel consumed. We re-read
        // from out? Cleanest: codebook passed implicitly via g_h + raw E.
    }
    // NOTE: E is staged from the const input pointer passed through g? We pass
    // emb via kernel arg instead:
    // (see vq_main2 wrapper below)
    (void)z; (void)out; (void)sCnt;
}

// real main kernel (takes emb pointer too)
__global__ void __launch_bounds__(512, 1)
vq_main2(const float* __restrict__ z, const float* __restrict__ emb,
         float* __restrict__ out) {
    extern __shared__ __align__(16) ull smemraw[];
    ull*   sE   = smemraw;                         // 128 KB
    float* sH   = (float*)(sE + NC * (CD / 2));
    float* sCnt = sH + NC;

    const ull* gE = (const ull*)emb;
    for (int i = threadIdx.x; i < NC * (CD / 2); i += 512) sE[i] = gE[i];
    for (int i = threadIdx.x; i < NC; i += 512) { sH[i] = g_h[i]; sCnt[i] = 0.0f; }
    __syncthreads();

    const int r = blockIdx.x * 512 + threadIdx.x;  // grid chosen so r < NROWS

    // load row into registers (packed pairs)
    ull f2[CD / 2];
    {
        const ulonglong2* fp = (const ulonglong2*)(z + (size_t)r * CD);
#pragma unroll
        for (int i = 0; i < CD / 4; i++) {
            ulonglong2 v = fp[i];
            f2[2 * i] = v.x; f2[2 * i + 1] = v.y;
        }
    }

    float best = -3.4e38f;
    int   bi   = 0;
#pragma unroll 1
    for (int j = 0; j < NC; j++) {
        const ulonglong2* e = (const ulonglong2*)(sE + j * (CD / 2));
        ull a0 = 0, a1 = 0, a2 = 0, a3 = 0;   // 0x0 == packed {+0.f,+0.f}
#pragma unroll
        for (int c = 0; c < CD / 8; c++) {    // 8 iters, 4 chains
            ulonglong2 v0 = e[2 * c];
            ulonglong2 v1 = e[2 * c + 1];
            fma2(a0, f2[4 * c + 0], v0.x);
            fma2(a1, f2[4 * c + 1], v0.y);
            fma2(a2, f2[4 * c + 2], v1.x);
            fma2(a3, f2[4 * c + 3], v1.y);
        }
        float2 p = unpack2(add2(add2(a0, a1), add2(a2, a3)));
        float s = (p.x + p.y) - sH[j];
        if (s > best) { best = s; bi = j; }    // strict '>' keeps lowest index
    }

    // ---- per-row epilogue ----
    out[O_IDX + r] = (float)bi;
    atomicAdd(&sCnt[bi], 1.0f);

    float*  orow = out + O_ZQ + (size_t)r * CD;
    float4* esum = (float4*)(g_esum + bi * CD);
    const ulonglong2* e = (const ulonglong2*)(sE + bi * (CD / 2));
    float lsse = 0.0f;
#pragma unroll
    for (int c = 0; c < CD / 4; c++) {
        ulonglong2 v = e[c];
        float2 e0 = unpack2(v.x), e1 = unpack2(v.y);
        float2 z0 = unpack2(f2[2 * c]), z1 = unpack2(f2[2 * c + 1]);
        float d0 = e0.x - z0.x, d1 = e0.y - z0.y;
        float d2 = e1.x - z1.x, d3 = e1.y - z1.y;
        lsse += d0 * d0 + d1 * d1 + d2 * d2 + d3 * d3;
        float4 q = make_float4(z0.x + d0, z0.y + d1, z1.x + d2, z1.y + d3);
        ((float4*)orow)[c] = q;
        // embed_sum accumulates FLAT (z), not e
        atomicAdd(&esum[c], make_float4(z0.x, z0.y, z1.x, z1.y));
    }

    // SSE: warp reduce, one global RED per warp
#pragma unroll
    for (int o = 16; o; o >>= 1) lsse += __shfl_xor_sync(0xffffffffu, lsse, o);
    if ((threadIdx.x & 31) == 0) atomicAdd(&g_sse, lsse);

    __syncthreads();
    for (int i = threadIdx.x; i < NC; i += 512) {
        float c = sCnt[i];
        if (c != 0.0f) atomicAdd(&g_counts[i], c);
    }
}

// ----------------------------------------------------------------------------
// Kernel 3: finalize EMA + loss. One block, 512 threads (one per code).
// ----------------------------------------------------------------------------
__global__ void vq_final(const float* __restrict__ cluster_size,
                         const float* __restrict__ embedding_avg,
                         float* __restrict__ out) {
    __shared__ float red[NC];
    const int j = threadIdx.x;

    float cnt = g_counts[j];
    float ncs = cluster_size[j] * 0.99f + 0.01f * cnt;
    out[O_NCS + j] = ncs;

    red[j] = ncs;
    __syncthreads();
#pragma unroll
    for (int o = NC / 2; o > 0; o >>= 1) {
        if (j < o) red[j] += red[j + o];
        __syncthreads();
    }
    float n  = red[0];
    float cs = (ncs + 1e-6f) / (n + (float)NC * 1e-6f);

#pragma unroll 4
    for (int k = 0; k < CD; k++) {
        float ea = embedding_avg[(size_t)j * CD + k] * 0.99f
                 + 0.01f * g_esum[(size_t)j * CD + k];
        out[O_NAVG + (size_t)j * CD + k] = ea;
        out[O_NEMB + (size_t)j * CD + k] = ea / cs;
    }

    if (j == 0) out[O_LOSS] = 0.25f * g_sse / (float)NELEM;
}

// ----------------------------------------------------------------------------
extern "C" void kernel_launch(void* const* d_in, const int* in_sizes, int n_in,
                              void* d_out, int out_size) {
    const float* z    = (const float*)d_in[0];  // [64,4096,64]
    const float* emb  = (const float*)d_in[1];  // [512,64]
    const float* csz  = (const float*)d_in[2];  // [512]
    const float* eavg = (const float*)d_in[3];  // [512,64]
    float* out = (float*)d_out;

    const int smem = NC * CD * 4 + NC * 4 + NC * 4;   // 135168 B
    cudaFuncSetAttribute(vq_main2, cudaFuncAttributeMaxDynamicSharedMemorySize, smem);

    vq_init<<<64, 512>>>(emb);
    vq_main2<<<NROWS / 512, 512, smem>>>(z, emb, out);
    vq_final<<<1, NC>>>(csz, eavg, out);
}